// round 3
// baseline (speedup 1.0000x reference)
#include <cuda_runtime.h>

#define BB   16
#define NN   4096
#define DD   64
#define NPT  1024
#define NSM  32
#define CNT_INV (1.0f/524288.0f)

// ---------------- device scratch (static: no allocation allowed) ----------------
__device__ int   g_fps[BB*NPT];
__device__ int   g_ball[BB*NPT*NSM];
__device__ float g_y1[(size_t)BB*NPT*64*NSM];   // 134 MB
__device__ float g_y2[(size_t)BB*NPT*64*NSM];   // 134 MB
__device__ float g_ymax[BB*NPT*128];            // 8 MB
__device__ float g_stats[512];   // L1: sum@0 sq@64 | L2: sum@128 sq@192 | L3: sum@256 sq@384
__device__ float g_aff[512];     // L1: sc@0 sh@64  | L2: sc@128 sh@192  | L3: sc@256 sh@384

__global__ void zero_stats_kernel() {
    int t = threadIdx.x;
    if (t < 512) g_stats[t] = 0.0f;
}

// ---------------- farthest point sampling: 1 block per batch ----------------
__global__ void fps_kernel(const float* __restrict__ xyz) {
    extern __shared__ float sh[];
    float* xs = sh; float* ys = sh + NN; float* zs = sh + 2*NN;
    __shared__ float wv[16];
    __shared__ int   wi[16];
    int b = blockIdx.x, tid = threadIdx.x;
    const float* xp = xyz + (size_t)b*NN*3;
    for (int t = tid; t < NN*3; t += 512) {
        float v = xp[t]; int i = t/3, c = t - 3*i;
        if (c == 0) xs[i] = v; else if (c == 1) ys[i] = v; else zs[i] = v;
    }
    float d[8];
    #pragma unroll
    for (int p = 0; p < 8; p++) d[p] = 1e10f;
    __syncthreads();

    int lane = tid & 31, w = tid >> 5;
    int far = 0;
    for (int j = 0; j < NPT; j++) {
        if (tid == 0) g_fps[b*NPT + j] = far;
        float cx = xs[far], cy = ys[far], cz = zs[far];
        float bv = -1.0f; int bi = 0;
        #pragma unroll
        for (int p = 0; p < 8; p++) {
            int i = tid + 512*p;
            float dx = xs[i]-cx, dy = ys[i]-cy, dz = zs[i]-cz;
            // replicate (x-c)**2 summed without fma contraction
            float s = __fadd_rn(__fadd_rn(__fmul_rn(dx,dx), __fmul_rn(dy,dy)), __fmul_rn(dz,dz));
            float dn = fminf(d[p], s);
            d[p] = dn;
            if (dn > bv) { bv = dn; bi = i; }
        }
        #pragma unroll
        for (int off = 16; off; off >>= 1) {
            float ov = __shfl_xor_sync(0xffffffffu, bv, off);
            int   oi = __shfl_xor_sync(0xffffffffu, bi, off);
            if (ov > bv || (ov == bv && oi < bi)) { bv = ov; bi = oi; }
        }
        if (lane == 0) { wv[w] = bv; wi[w] = bi; }
        __syncthreads();
        bv = wv[0]; bi = wi[0];
        #pragma unroll
        for (int t = 1; t < 16; t++) {
            float ov = wv[t]; int oi = wi[t];
            if (ov > bv || (ov == bv && oi < bi)) { bv = ov; bi = oi; }
        }
        far = bi;
        __syncthreads();
    }
}

// ---------------- ball query: 1 block per batch, 1 warp per centroid ----------------
__global__ void ball_kernel(const float* __restrict__ xyz, float* __restrict__ out) {
    extern __shared__ float sh[];
    float* xs = sh; float* ys = sh + NN; float* zs = sh + 2*NN; float* nn = sh + 3*NN;
    int b = blockIdx.x, tid = threadIdx.x;
    const float* xp = xyz + (size_t)b*NN*3;
    for (int t = tid; t < NN*3; t += 1024) {
        float v = xp[t]; int i = t/3, c = t - 3*i;
        if (c == 0) xs[i] = v; else if (c == 1) ys[i] = v; else zs[i] = v;
    }
    __syncthreads();
    for (int i = tid; i < NN; i += 1024)
        nn[i] = __fadd_rn(__fadd_rn(__fmul_rn(xs[i],xs[i]), __fmul_rn(ys[i],ys[i])), __fmul_rn(zs[i],zs[i]));
    __syncthreads();

    int w = tid >> 5, lane = tid & 31;
    const float r2 = 0.04f;
    for (int j = w; j < NPT; j += 32) {
        int fidx = g_fps[b*NPT + j];
        float cx = xs[fidx], cy = ys[fidx], cz = zs[fidx], cn = nn[fidx];
        if (lane == 0) {
            float* o = out + (size_t)(b*NPT + j)*3;
            o[0] = cx; o[1] = cy; o[2] = cz;
        }
        int cnt = 0, first = -1;
        int* bo = g_ball + (size_t)(b*NPT + j)*NSM;
        for (int base = 0; base < NN; base += 32) {
            int i = base + lane;
            // replicate -2*dot + |src|^2 + |dst|^2, no contraction
            float dot = __fadd_rn(__fadd_rn(__fmul_rn(cx,xs[i]), __fmul_rn(cy,ys[i])), __fmul_rn(cz,zs[i]));
            float sq  = __fadd_rn(__fadd_rn(__fmul_rn(-2.0f,dot), cn), nn[i]);
            bool ok = (sq <= r2);
            unsigned m = __ballot_sync(0xffffffffu, ok);
            if (first < 0 && m) first = base + __ffs(m) - 1;
            int pos = cnt + __popc(m & ((1u << lane) - 1u));
            if (ok && pos < NSM) bo[pos] = i;
            cnt += __popc(m);
            if (cnt >= NSM) break;
        }
        if (cnt < NSM && lane >= cnt) bo[lane] = first;
    }
}

// ---------------- conv1: gather + 67->64 GEMV, stats ----------------
__global__ void conv1_kernel(const float* __restrict__ xyz, const float* __restrict__ pts,
                             const float* __restrict__ w1,  const float* __restrict__ b1,
                             const float* __restrict__ nxyz) {
    __shared__ float ws[64*68];
    __shared__ float bs[64], ssum[64], ssq[64];
    int tid = threadIdx.x;
    for (int t = tid; t < 64*67; t += 256) { int c = t/67, k = t - 67*c; ws[c*68 + k] = w1[t]; }
    for (int t = tid; t < 64; t += 256) { bs[t] = b1[t]; ssum[t] = 0.f; ssq[t] = 0.f; }
    __syncthreads();

    int w = tid >> 5, lane = tid & 31;
    int bj = blockIdx.x*8 + w;
    int b  = bj >> 10;
    int idx = g_ball[(size_t)bj*NSM + lane];
    const float* xp = xyz  + (size_t)(b*NN + idx)*3;
    const float* cp = nxyz + (size_t)bj*3;
    float f[67];
    f[0] = xp[0]-cp[0]; f[1] = xp[1]-cp[1]; f[2] = xp[2]-cp[2];
    const float* pp = pts + (size_t)(b*NN + idx)*DD;
    #pragma unroll
    for (int k = 0; k < 64; k++) f[3+k] = pp[k];

    float* yo = g_y1 + (size_t)bj*64*NSM;
    for (int c = 0; c < 64; c++) {
        const float* wr = ws + c*68;
        float a0 = 0.f, a1 = 0.f, a2 = 0.f, a3 = 0.f;
        #pragma unroll
        for (int k = 0; k < 64; k += 4) {
            a0 = fmaf(wr[k+0], f[k+0], a0);
            a1 = fmaf(wr[k+1], f[k+1], a1);
            a2 = fmaf(wr[k+2], f[k+2], a2);
            a3 = fmaf(wr[k+3], f[k+3], a3);
        }
        a0 = fmaf(wr[64], f[64], a0);
        a1 = fmaf(wr[65], f[65], a1);
        a2 = fmaf(wr[66], f[66], a2);
        float y = ((a0+a1) + (a2+a3)) + bs[c];
        yo[c*NSM + lane] = y;
        float s = y, q = y*y;
        #pragma unroll
        for (int off = 16; off; off >>= 1) {
            s += __shfl_xor_sync(0xffffffffu, s, off);
            q += __shfl_xor_sync(0xffffffffu, q, off);
        }
        if (lane == 0) { atomicAdd(&ssum[c], s); atomicAdd(&ssq[c], q); }
    }
    __syncthreads();
    for (int t = tid; t < 64; t += 256) {
        atomicAdd(&g_stats[t],      ssum[t]);
        atomicAdd(&g_stats[64 + t], ssq[t]);
    }
}

// ---------------- conv2: BN1+ReLU fused on load, 64->64 GEMV, stats ----------------
__global__ void conv2_kernel(const float* __restrict__ w2, const float* __restrict__ b2) {
    __shared__ float ws[64*64];
    __shared__ float bs[64], sc[64], sf[64], ssum[64], ssq[64];
    int tid = threadIdx.x;
    for (int t = tid; t < 64*64; t += 256) ws[t] = w2[t];
    for (int t = tid; t < 64; t += 256) {
        bs[t] = b2[t]; sc[t] = g_aff[t]; sf[t] = g_aff[64 + t];
        ssum[t] = 0.f; ssq[t] = 0.f;
    }
    __syncthreads();

    int w = tid >> 5, lane = tid & 31;
    int bj = blockIdx.x*8 + w;
    const float* yi = g_y1 + (size_t)bj*64*NSM;
    float f[64];
    #pragma unroll
    for (int k = 0; k < 64; k++)
        f[k] = fmaxf(fmaf(yi[k*NSM + lane], sc[k], sf[k]), 0.0f);

    float* yo = g_y2 + (size_t)bj*64*NSM;
    for (int c = 0; c < 64; c++) {
        const float* wr = ws + c*64;
        float a0 = 0.f, a1 = 0.f, a2 = 0.f, a3 = 0.f;
        #pragma unroll
        for (int k = 0; k < 64; k += 4) {
            a0 = fmaf(wr[k+0], f[k+0], a0);
            a1 = fmaf(wr[k+1], f[k+1], a1);
            a2 = fmaf(wr[k+2], f[k+2], a2);
            a3 = fmaf(wr[k+3], f[k+3], a3);
        }
        float y = ((a0+a1) + (a2+a3)) + bs[c];
        yo[c*NSM + lane] = y;
        float s = y, q = y*y;
        #pragma unroll
        for (int off = 16; off; off >>= 1) {
            s += __shfl_xor_sync(0xffffffffu, s, off);
            q += __shfl_xor_sync(0xffffffffu, q, off);
        }
        if (lane == 0) { atomicAdd(&ssum[c], s); atomicAdd(&ssq[c], q); }
    }
    __syncthreads();
    for (int t = tid; t < 64; t += 256) {
        atomicAdd(&g_stats[128 + t], ssum[t]);
        atomicAdd(&g_stats[192 + t], ssq[t]);
    }
}

// ---------------- conv3: BN2+ReLU fused, 64->128 GEMV, per-channel max + stats ----------------
__global__ void conv3_kernel(const float* __restrict__ w3, const float* __restrict__ b3) {
    __shared__ float ws[128*64];
    __shared__ float bs[128], sc[64], sf[64], ssum[128], ssq[128];
    int tid = threadIdx.x;
    for (int t = tid; t < 128*64; t += 256) ws[t] = w3[t];
    for (int t = tid; t < 128; t += 256) { bs[t] = b3[t]; ssum[t] = 0.f; ssq[t] = 0.f; }
    for (int t = tid; t < 64; t += 256)  { sc[t] = g_aff[128 + t]; sf[t] = g_aff[192 + t]; }
    __syncthreads();

    int w = tid >> 5, lane = tid & 31;
    int bj = blockIdx.x*8 + w;
    const float* yi = g_y2 + (size_t)bj*64*NSM;
    float f[64];
    #pragma unroll
    for (int k = 0; k < 64; k++)
        f[k] = fmaxf(fmaf(yi[k*NSM + lane], sc[k], sf[k]), 0.0f);

    for (int c = 0; c < 128; c++) {
        const float* wr = ws + c*64;
        float a0 = 0.f, a1 = 0.f, a2 = 0.f, a3 = 0.f;
        #pragma unroll
        for (int k = 0; k < 64; k += 4) {
            a0 = fmaf(wr[k+0], f[k+0], a0);
            a1 = fmaf(wr[k+1], f[k+1], a1);
            a2 = fmaf(wr[k+2], f[k+2], a2);
            a3 = fmaf(wr[k+3], f[k+3], a3);
        }
        float y = ((a0+a1) + (a2+a3)) + bs[c];
        float s = y, q = y*y, m = y;
        #pragma unroll
        for (int off = 16; off; off >>= 1) {
            s += __shfl_xor_sync(0xffffffffu, s, off);
            q += __shfl_xor_sync(0xffffffffu, q, off);
            m  = fmaxf(m, __shfl_xor_sync(0xffffffffu, m, off));
        }
        if (lane == 0) {
            g_ymax[bj*128 + c] = m;
            atomicAdd(&ssum[c], s); atomicAdd(&ssq[c], q);
        }
    }
    __syncthreads();
    for (int t = tid; t < 128; t += 256) {
        atomicAdd(&g_stats[256 + t], ssum[t]);
        atomicAdd(&g_stats[384 + t], ssq[t]);
    }
}

// ---------------- BN finalize: scale/shift ----------------
__global__ void finalize_kernel(const float* __restrict__ g, const float* __restrict__ beta,
                                int C, int sumOff, int sqOff, int affOff) {
    int t = threadIdx.x;
    if (t < C) {
        float mean = g_stats[sumOff + t] * CNT_INV;
        float var  = g_stats[sqOff + t]  * CNT_INV - mean*mean;
        float inv  = rsqrtf(var + 1e-5f);
        float s = g[t] * inv;
        g_aff[affOff + t]     = s;
        g_aff[affOff + C + t] = beta[t] - mean*s;
    }
}

// ---------------- output: BN3+ReLU applied to per-channel max (monotone, g>0) ----------------
__global__ void out_kernel(float* __restrict__ out) {
    int i = blockIdx.x*blockDim.x + threadIdx.x;
    if (i < BB*NPT*128) {
        int c = i & 127;
        float v = fmaf(g_ymax[i], g_aff[256 + c], g_aff[384 + c]);
        out[BB*NPT*3 + i] = fmaxf(v, 0.0f);
    }
}

extern "C" void kernel_launch(void* const* d_in, const int* in_sizes, int n_in,
                              void* d_out, int out_size) {
    const float* xyz = (const float*)d_in[0];
    const float* pts = (const float*)d_in[1];
    const float* w1  = (const float*)d_in[2];
    const float* b1  = (const float*)d_in[3];
    const float* g1  = (const float*)d_in[4];
    const float* be1 = (const float*)d_in[5];
    const float* w2  = (const float*)d_in[6];
    const float* b2  = (const float*)d_in[7];
    const float* g2  = (const float*)d_in[8];
    const float* be2 = (const float*)d_in[9];
    const float* w3  = (const float*)d_in[10];
    const float* b3  = (const float*)d_in[11];
    const float* g3  = (const float*)d_in[12];
    const float* be3 = (const float*)d_in[13];
    float* out = (float*)d_out;

    cudaFuncSetAttribute(fps_kernel,  cudaFuncAttributeMaxDynamicSharedMemorySize, 3*NN*4);
    cudaFuncSetAttribute(ball_kernel, cudaFuncAttributeMaxDynamicSharedMemorySize, 4*NN*4);

    zero_stats_kernel<<<1, 512>>>();
    fps_kernel<<<BB, 512, 3*NN*4>>>(xyz);
    ball_kernel<<<BB, 1024, 4*NN*4>>>(xyz, out);
    conv1_kernel<<<BB*NPT/8, 256>>>(xyz, pts, w1, b1, out);
    finalize_kernel<<<1, 64>>>(g1, be1, 64, 0, 64, 0);
    conv2_kernel<<<BB*NPT/8, 256>>>(w2, b2);
    finalize_kernel<<<1, 64>>>(g2, be2, 64, 128, 192, 128);
    conv3_kernel<<<BB*NPT/8, 256>>>(w3, b3);
    finalize_kernel<<<1, 128>>>(g3, be3, 128, 256, 384, 256);
    out_kernel<<<(BB*NPT*128 + 255)/256, 256>>>(out);
}